// round 1
// baseline (speedup 1.0000x reference)
#include <cuda_runtime.h>
#include <cuda_bf16.h>

#define NN 2048
#define TN 8
#define TJ 32

// Scratch (device globals; no allocation allowed)
__device__ float g_h [2 * NN * 128];   // h[b][n][128]
__device__ float g_v [2 * NN * 128];   // vperm[b][j][h][d]
__device__ float g_ei[2 * NN * 4];
__device__ float g_ej[2 * NN * 4];

// ---------------------------------------------------------------------------
// Kernel 1: h = x @ w^T, scatter permuted v, compute ei/ej.
// 512 blocks x 128 threads; each block handles 8 rows (b*N+n flattened).
// ---------------------------------------------------------------------------
__global__ __launch_bounds__(128) void k1_proj(const float* __restrict__ x,
                                               const float* __restrict__ w,
                                               const float* __restrict__ a) {
    const int t    = threadIdx.x;       // 0..127 = output column (h,d)
    const int r0   = blockIdx.x * 8;    // first row of this block
    const int h    = t >> 5;
    const int d    = t & 31;
    const int lane = t & 31;

    __shared__ float ws[128 * 65];      // padded w to avoid bank conflicts
    __shared__ float xs[8 * 64];

#pragma unroll
    for (int k = 0; k < 64; ++k) {
        int idx = t + k * 128;          // 0..8191
        ws[(idx >> 6) * 65 + (idx & 63)] = w[idx];
    }
#pragma unroll
    for (int k = 0; k < 4; ++k)
        xs[t + k * 128] = x[r0 * 64 + t + k * 128];
    __syncthreads();

    const float a1v = a[h * 64 + d];
    const float a2v = a[h * 64 + 32 + d];
    const float* wrow = &ws[t * 65];

    for (int rr = 0; rr < 8; ++rr) {
        const int row = r0 + rr;        // = b*NN + n
        float acc = 0.f;
#pragma unroll
        for (int i = 0; i < 64; ++i)
            acc += xs[rr * 64 + i] * wrow[i];

        g_h[row * 128 + t] = acc;

        // vperm scatter: v[b,j,hq,d] = h[b,n,h,d] with j*4+hq = h*NN + n
        const int b   = row >> 11;
        const int n   = row & (NN - 1);
        const int idx = h * NN + n;
        g_v[(b * NN + (idx >> 2)) * 128 + (idx & 3) * 32 + d] = acc;

        // ei/ej: warp = one head, butterfly reduce over D=32
        float p1 = acc * a1v;
        float p2 = acc * a2v;
#pragma unroll
        for (int off = 16; off; off >>= 1) {
            p1 += __shfl_xor_sync(0xffffffffu, p1, off);
            p2 += __shfl_xor_sync(0xffffffffu, p2, off);
        }
        if (lane == 0) {
            g_ei[row * 4 + h] = p1;
            g_ej[row * 4 + h] = p2;
        }
    }
}

// ---------------------------------------------------------------------------
// Kernel 2: fused masked-softmax attention + residual + LayerNorm.
// Grid: 512 blocks = (B=2) x (N/TN=256). 128 threads = one output column
// (h,d) each; acc[TN] rows in registers. Single-pass softmax (no max-sub;
// e is bounded so exp is safe in fp32).
// ---------------------------------------------------------------------------
__global__ __launch_bounds__(128) void k2_attn(const int*   __restrict__ adj,
                                               const float* __restrict__ gamma,
                                               const float* __restrict__ beta,
                                               float*       __restrict__ out) {
    const int t  = threadIdx.x;
    const int b  = blockIdx.x >> 8;            // /256
    const int n0 = (blockIdx.x & 255) * TN;
    const int h  = t >> 5;
    const int d  = t & 31;

    __shared__ float eis[TN * 4];
    __shared__ float ejs[TJ * 4];
    __shared__ int   adjs[TN * TJ];
    __shared__ float P[TJ][64];                // [jj][r*4+h]
    __shared__ float ssum[128];
    __shared__ float rs[64];
    __shared__ float red1[4][TN], red2[4][TN];

    if (t < TN * 4)
        eis[t] = g_ei[(b * NN + n0 + (t >> 2)) * 4 + (t & 3)];

    float acc[TN];
#pragma unroll
    for (int r = 0; r < TN; ++r) acc[r] = 0.f;
    float psum[16];
#pragma unroll
    for (int k = 0; k < 16; ++k) psum[k] = 0.f;

    const int rh = t & 63;                     // fixed (r,h) slot per thread
    const int rr = rh >> 2;
    const int hh = rh & 3;
    const int jbase = t >> 6;                  // 0 or 1 (jj parity)

    for (int j0 = 0; j0 < NN; j0 += TJ) {
        // stage ej tile: 128 consecutive floats
        ejs[t] = g_ej[(b * NN + j0) * 4 + t];
        // stage adj tile: TN x TJ ints, coalesced in 32-chunks
#pragma unroll
        for (int k = 0; k < 2; ++k) {
            int idx = t + k * 128;             // 0..255
            int r = idx >> 5, jj = idx & 31;
            adjs[idx] = adj[(n0 + r) * NN + j0 + jj];
        }
        __syncthreads();

        // P stage: 16 values per thread at fixed rh, jj = jbase + 2k
        const float ei_v = eis[rh];
#pragma unroll
        for (int k = 0; k < 16; ++k) {
            int jj = jbase + 2 * k;
            float e = ei_v + ejs[jj * 4 + hh];
            e = e > 0.f ? e : 0.2f * e;
            float p = adjs[rr * TJ + jj] ? __expf(e) : 0.f;
            P[jj][rh] = p;
            psum[k] += p;
        }
        __syncthreads();

        // accumulate: thread column t, vperm row-contiguous loads
        const float* vcol = &g_v[(b * NN + j0) * 128 + t];
#pragma unroll 4
        for (int jj = 0; jj < TJ; ++jj) {
            float vv = vcol[jj * 128];
#pragma unroll
            for (int r = 0; r < TN; ++r)
                acc[r] += P[jj][r * 4 + h] * vv;   // broadcast smem read
        }
        __syncthreads();
    }

    // softmax denominators: rs[rh] = thread(rh) + thread(rh+64)
    float s = 0.f;
#pragma unroll
    for (int k = 0; k < 16; ++k) s += psum[k];
    ssum[t] = s;
    __syncthreads();
    if (t < 64) rs[t] = ssum[t] + ssum[t + 64];
    __syncthreads();

    // epilogue: normalize, residual, LayerNorm
    const float gma = gamma[t];
    const float bta = beta[t];
    float ys[TN];
#pragma unroll
    for (int r = 0; r < TN; ++r) {
        float hp = acc[r] / rs[r * 4 + h];
        float y  = hp + g_h[(b * NN + n0 + r) * 128 + t];
        ys[r] = y;
        float s1 = y, s2 = y * y;
#pragma unroll
        for (int off = 16; off; off >>= 1) {
            s1 += __shfl_xor_sync(0xffffffffu, s1, off);
            s2 += __shfl_xor_sync(0xffffffffu, s2, off);
        }
        if (d == 0) { red1[h][r] = s1; red2[h][r] = s2; }
    }
    __syncthreads();
#pragma unroll
    for (int r = 0; r < TN; ++r) {
        float s1 = red1[0][r] + red1[1][r] + red1[2][r] + red1[3][r];
        float s2 = red2[0][r] + red2[1][r] + red2[2][r] + red2[3][r];
        float mu  = s1 * (1.f / 128.f);
        float var = s2 * (1.f / 128.f) - mu * mu;
        float inv = rsqrtf(var + 1e-5f);
        out[(b * NN + n0 + r) * 128 + t] = (ys[r] - mu) * inv * gma + bta;
    }
}

extern "C" void kernel_launch(void* const* d_in, const int* in_sizes, int n_in,
                              void* d_out, int out_size) {
    const float* x     = (const float*)d_in[0];
    const int*   adj   = (const int*)  d_in[1];
    const float* w     = (const float*)d_in[2];
    const float* a     = (const float*)d_in[3];
    const float* gamma = (const float*)d_in[4];
    const float* beta  = (const float*)d_in[5];

    k1_proj<<<512, 128>>>(x, w, a);
    k2_attn<<<512, 128>>>(adj, gamma, beta, (float*)d_out);
}

// round 3
// speedup vs baseline: 2.2804x; 2.2804x over previous
#include <cuda_runtime.h>
#include <cuda_bf16.h>

#define NN 2048
#define TN 16
#define TJ 32
#define SPLIT 4
#define JCHUNK (NN / SPLIT)

typedef unsigned long long ull;

// Scratch (device globals; no allocation allowed)
__device__ float g_h   [2 * NN * 128];          // h[b][n][128]
__device__ float g_v   [2 * NN * 128];          // vperm[b][j][h][d]
__device__ float g_ei  [2 * NN * 4];
__device__ float g_ej  [2 * NN * 4];
__device__ float g_part[SPLIT * 2 * NN * 128];  // partial AV accumulators
__device__ float g_psum[SPLIT * 2 * NN * 4];    // partial softmax denominators

// ---------------------------------------------------------------------------
// Kernel 1: h = x @ w^T, scatter permuted v, compute ei/ej.
// ---------------------------------------------------------------------------
__global__ __launch_bounds__(128) void k1_proj(const float* __restrict__ x,
                                               const float* __restrict__ w,
                                               const float* __restrict__ a) {
    const int t    = threadIdx.x;       // 0..127 = output column (h,d)
    const int r0   = blockIdx.x * 8;
    const int h    = t >> 5;
    const int d    = t & 31;
    const int lane = t & 31;

    __shared__ float ws[128 * 65];
    __shared__ float xs[8 * 64];

#pragma unroll
    for (int k = 0; k < 64; ++k) {
        int idx = t + k * 128;
        ws[(idx >> 6) * 65 + (idx & 63)] = w[idx];
    }
#pragma unroll
    for (int k = 0; k < 4; ++k)
        xs[t + k * 128] = x[r0 * 64 + t + k * 128];
    __syncthreads();

    const float a1v = a[h * 64 + d];
    const float a2v = a[h * 64 + 32 + d];
    const float* wrow = &ws[t * 65];

    for (int rr = 0; rr < 8; ++rr) {
        const int row = r0 + rr;        // = b*NN + n
        float acc = 0.f;
#pragma unroll
        for (int i = 0; i < 64; ++i)
            acc += xs[rr * 64 + i] * wrow[i];

        g_h[row * 128 + t] = acc;

        // vperm scatter: v[b,j,hq,d] = h[b,n,h,d] with j*4+hq = h*NN + n
        const int b   = row >> 11;
        const int n   = row & (NN - 1);
        const int idx = h * NN + n;
        g_v[(b * NN + (idx >> 2)) * 128 + (idx & 3) * 32 + d] = acc;

        float p1 = acc * a1v;
        float p2 = acc * a2v;
#pragma unroll
        for (int off = 16; off; off >>= 1) {
            p1 += __shfl_xor_sync(0xffffffffu, p1, off);
            p2 += __shfl_xor_sync(0xffffffffu, p2, off);
        }
        if (lane == 0) {
            g_ei[row * 4 + h] = p1;
            g_ej[row * 4 + h] = p2;
        }
    }
}

// ---------------------------------------------------------------------------
// Kernel 2: masked-softmax attention, split-j partials.
// Grid: 1024 = B(2) x ntiles(128, TN=16 rows) x SPLIT(4).
// 128 threads: tp = t&63 owns column pair (2tp, 2tp+1); rg = t>>6 owns
// row-group of 8. P stored in smem duplicated as float2{p,p} so the AV
// inner loop is LDS.64 + fma.rn.f32x2 (packed FFMA2).
// ---------------------------------------------------------------------------
__global__ __launch_bounds__(128) void k2_attn(const int* __restrict__ adj) {
    const int t  = threadIdx.x;
    const int sp = blockIdx.x & (SPLIT - 1);
    const int nt = (blockIdx.x >> 2) & 127;
    const int b  = blockIdx.x >> 9;
    const int n0 = nt * TN;
    const int js = sp * JCHUNK;

    const int tp = t & 63;              // column pair id: cols 2tp, 2tp+1
    const int rg = t >> 6;              // row group (rows rg*8 .. rg*8+7)
    const int h4 = tp >> 4;             // head of this column pair

    const int rh     = t & 63;          // P-stage slot: r = rh>>2, h = rh&3
    const int parity = t >> 6;
    const int rr_p   = rh >> 2;
    const int hh_p   = rh & 3;

    __shared__ float  eis[TN * 4];      // 64
    __shared__ float  ejs[TJ * 4];      // 128
    __shared__ int    adjs[TN * TJ];    // 512
    __shared__ float2 Pd[TJ][64];       // 16KB, duplicated pairs
    __shared__ float  ssum[128];

    if (t < 64)
        eis[t] = g_ei[(b * NN + n0 + (t >> 2)) * 4 + (t & 3)];

    ull acc2[8];
#pragma unroll
    for (int r = 0; r < 8; ++r) acc2[r] = 0ull;
    float psum[16];
#pragma unroll
    for (int k = 0; k < 16; ++k) psum[k] = 0.f;

    for (int j0 = js; j0 < js + JCHUNK; j0 += TJ) {
        ejs[t] = g_ej[(b * NN + j0) * 4 + t];
#pragma unroll
        for (int k = 0; k < 4; ++k) {
            int idx = t + k * 128;                 // 0..511
            int r = idx >> 5, jj = idx & 31;
            adjs[idx] = adj[(n0 + r) * NN + j0 + jj];
        }
        __syncthreads();

        // P stage: 16 exps per thread at fixed rh, jj = parity + 2k
        const float ei_v = eis[rh];
#pragma unroll
        for (int k = 0; k < 16; ++k) {
            int jj = parity + 2 * k;
            float e = ei_v + ejs[jj * 4 + hh_p];
            e = e > 0.f ? e : 0.2f * e;
            float p = adjs[rr_p * TJ + jj] ? __expf(e) : 0.f;
            Pd[jj][rh] = make_float2(p, p);
            psum[k] += p;
        }
        __syncthreads();

        // AV accumulate: packed fp32x2 FMA
        const ull* vptr = (const ull*)(g_v + (size_t)(b * NN + j0) * 128) + tp;
#pragma unroll 4
        for (int jj = 0; jj < TJ; ++jj) {
            ull v2 = vptr[jj * 64];
            const ull* prow = (const ull*)&Pd[jj][0];
#pragma unroll
            for (int r = 0; r < 8; ++r) {
                ull p2 = prow[(rg * 8 + r) * 4 + h4];
                asm("fma.rn.f32x2 %0, %1, %2, %0;" : "+l"(acc2[r]) : "l"(p2), "l"(v2));
            }
        }
        __syncthreads();
    }

    // partial softmax denominators
    float s = 0.f;
#pragma unroll
    for (int k = 0; k < 16; ++k) s += psum[k];
    ssum[t] = s;
    __syncthreads();
    if (t < 64) {
        float rsp = ssum[t] + ssum[t + 64];        // slot rh = t
        g_psum[((sp * 2 + b) * NN + n0 + (t >> 2)) * 4 + (t & 3)] = rsp;
    }

    // partial AV accumulators
#pragma unroll
    for (int r = 0; r < 8; ++r) {
        int row = n0 + rg * 8 + r;
        ull* dst = (ull*)g_part + (size_t)((sp * 2 + b) * NN + row) * 64 + tp;
        *dst = acc2[r];
    }
}

// ---------------------------------------------------------------------------
// Kernel 3: reduce split partials, normalize, residual, LayerNorm.
// 512 blocks x 128 thr; 8 rows per block, thread = output column.
// ---------------------------------------------------------------------------
__global__ __launch_bounds__(128) void k3_epi(const float* __restrict__ gamma,
                                              const float* __restrict__ beta,
                                              float*       __restrict__ out) {
    const int t  = threadIdx.x;
    const int b  = blockIdx.x >> 8;
    const int n0 = (blockIdx.x & 255) * 8;
    const int h  = t >> 5;
    const int d  = t & 31;

    __shared__ float red1[4][8], red2[4][8];

    const float gma = gamma[t];
    const float bta = beta[t];
    float ys[8];

#pragma unroll
    for (int r = 0; r < 8; ++r) {
        const int n = n0 + r;
        float accv = 0.f, rsum = 0.f;
#pragma unroll
        for (int spp = 0; spp < SPLIT; ++spp) {
            accv += g_part[(size_t)((spp * 2 + b) * NN + n) * 128 + t];
            rsum += g_psum[((spp * 2 + b) * NN + n) * 4 + h];
        }
        float y = accv / rsum + g_h[(b * NN + n) * 128 + t];
        ys[r] = y;
        float s1 = y, s2 = y * y;
#pragma unroll
        for (int off = 16; off; off >>= 1) {
            s1 += __shfl_xor_sync(0xffffffffu, s1, off);
            s2 += __shfl_xor_sync(0xffffffffu, s2, off);
        }
        if (d == 0) { red1[h][r] = s1; red2[h][r] = s2; }
    }
    __syncthreads();
#pragma unroll
    for (int r = 0; r < 8; ++r) {
        float s1 = red1[0][r] + red1[1][r] + red1[2][r] + red1[3][r];
        float s2 = red2[0][r] + red2[1][r] + red2[2][r] + red2[3][r];
        float mu  = s1 * (1.f / 128.f);
        float var = s2 * (1.f / 128.f) - mu * mu;
        float inv = rsqrtf(var + 1e-5f);
        out[(b * NN + n0 + r) * 128 + t] = (ys[r] - mu) * inv * gma + bta;
    }
}

extern "C" void kernel_launch(void* const* d_in, const int* in_sizes, int n_in,
                              void* d_out, int out_size) {
    const float* x     = (const float*)d_in[0];
    const int*   adj   = (const int*)  d_in[1];
    const float* w     = (const float*)d_in[2];
    const float* a     = (const float*)d_in[3];
    const float* gamma = (const float*)d_in[4];
    const float* beta  = (const float*)d_in[5];

    k1_proj<<<512, 128>>>(x, w, a);
    k2_attn<<<2 * 128 * SPLIT, 128>>>(adj);
    k3_epi<<<512, 128>>>(gamma, beta, (float*)d_out);
}

// round 4
// speedup vs baseline: 2.3530x; 1.0318x over previous
#include <cuda_runtime.h>
#include <cuda_bf16.h>

#define NN 2048
#define TN 16
#define TJ 32
#define SPLIT 8
#define JCHUNK (NN / SPLIT)

typedef unsigned long long ull;

// Scratch (device globals; no allocation allowed)
__device__ float g_h   [2 * NN * 128];          // h[b][n][128]
__device__ float g_v   [2 * NN * 128];          // vperm[b][j][h][d]
__device__ float g_ei  [2 * NN * 4];
__device__ float g_ej  [2 * NN * 4];
__device__ float g_part[SPLIT * 2 * NN * 128];  // partial AV accumulators
__device__ float g_psum[SPLIT * 2 * NN * 4];    // partial softmax denominators

// ---------------------------------------------------------------------------
// Kernel 1: h = x @ w^T, scatter permuted v, compute ei/ej.
// ---------------------------------------------------------------------------
__global__ __launch_bounds__(128) void k1_proj(const float* __restrict__ x,
                                               const float* __restrict__ w,
                                               const float* __restrict__ a) {
    const int t    = threadIdx.x;       // 0..127 = output column (h,d)
    const int r0   = blockIdx.x * 8;
    const int h    = t >> 5;
    const int d    = t & 31;
    const int lane = t & 31;

    __shared__ float ws[128 * 65];
    __shared__ float xs[8 * 64];

#pragma unroll
    for (int k = 0; k < 64; ++k) {
        int idx = t + k * 128;
        ws[(idx >> 6) * 65 + (idx & 63)] = w[idx];
    }
#pragma unroll
    for (int k = 0; k < 4; ++k)
        xs[t + k * 128] = x[r0 * 64 + t + k * 128];
    __syncthreads();

    const float a1v = a[h * 64 + d];
    const float a2v = a[h * 64 + 32 + d];
    const float* wrow = &ws[t * 65];

    for (int rr = 0; rr < 8; ++rr) {
        const int row = r0 + rr;        // = b*NN + n
        float acc = 0.f;
#pragma unroll
        for (int i = 0; i < 64; ++i)
            acc += xs[rr * 64 + i] * wrow[i];

        g_h[row * 128 + t] = acc;

        // vperm scatter: v[b,j,hq,d] = h[b,n,h,d] with j*4+hq = h*NN + n
        const int b   = row >> 11;
        const int n   = row & (NN - 1);
        const int idx = h * NN + n;
        g_v[(b * NN + (idx >> 2)) * 128 + (idx & 3) * 32 + d] = acc;

        float p1 = acc * a1v;
        float p2 = acc * a2v;
#pragma unroll
        for (int off = 16; off; off >>= 1) {
            p1 += __shfl_xor_sync(0xffffffffu, p1, off);
            p2 += __shfl_xor_sync(0xffffffffu, p2, off);
        }
        if (lane == 0) {
            g_ei[row * 4 + h] = p1;
            g_ej[row * 4 + h] = p2;
        }
    }
}

// ---------------------------------------------------------------------------
// Kernel 2: masked-softmax attention, split-j partials.
// Grid: 2048 = B(2) x ntiles(128, TN=16 rows) x SPLIT(8).
// 128 threads: tp = t&63 owns column pair (2tp, 2tp+1); rg = t>>6 owns
// row-group of 8. P stored in smem duplicated as float2{p,p} so the AV
// inner loop is LDS.64 + fma.rn.f32x2 (packed FFMA2).
// ---------------------------------------------------------------------------
__global__ __launch_bounds__(128) void k2_attn(const int* __restrict__ adj) {
    const int t  = threadIdx.x;
    const int sp = blockIdx.x & (SPLIT - 1);
    const int nt = (blockIdx.x >> 3) & 127;
    const int b  = blockIdx.x >> 10;
    const int n0 = nt * TN;
    const int js = sp * JCHUNK;

    const int tp = t & 63;              // column pair id: cols 2tp, 2tp+1
    const int rg = t >> 6;              // row group (rows rg*8 .. rg*8+7)
    const int h4 = tp >> 4;             // head of this column pair

    const int rh     = t & 63;          // P-stage slot: r = rh>>2, h = rh&3
    const int parity = t >> 6;
    const int rr_p   = rh >> 2;
    const int hh_p   = rh & 3;

    __shared__ float  eis[TN * 4];      // 64
    __shared__ float  ejs[TJ * 4];      // 128
    __shared__ int    adjs[TN * TJ];    // 512
    __shared__ float2 Pd[TJ][64];       // 16KB, duplicated pairs
    __shared__ float  ssum[128];

    if (t < 64)
        eis[t] = g_ei[(b * NN + n0 + (t >> 2)) * 4 + (t & 3)];

    ull acc2[8];
#pragma unroll
    for (int r = 0; r < 8; ++r) acc2[r] = 0ull;
    float psum[8];
#pragma unroll
    for (int k = 0; k < 8; ++k) psum[k] = 0.f;
    float psum2 = 0.f;

    for (int j0 = js; j0 < js + JCHUNK; j0 += TJ) {
        ejs[t] = g_ej[(b * NN + j0) * 4 + t];
#pragma unroll
        for (int k = 0; k < 4; ++k) {
            int idx = t + k * 128;                 // 0..511
            int r = idx >> 5, jj = idx & 31;
            adjs[idx] = adj[(n0 + r) * NN + j0 + jj];
        }
        __syncthreads();

        // P stage: 16 exps per thread at fixed rh, jj = parity + 2k
        const float ei_v = eis[rh];
#pragma unroll
        for (int k = 0; k < 16; ++k) {
            int jj = parity + 2 * k;
            float e = ei_v + ejs[jj * 4 + hh_p];
            e = e > 0.f ? e : 0.2f * e;
            float p = adjs[rr_p * TJ + jj] ? __expf(e) : 0.f;
            Pd[jj][rh] = make_float2(p, p);
            if (k < 8) psum[k] += p; else psum2 += p;
        }
        __syncthreads();

        // AV accumulate: packed fp32x2 FMA
        const ull* vptr = (const ull*)(g_v + (size_t)(b * NN + j0) * 128) + tp;
#pragma unroll 4
        for (int jj = 0; jj < TJ; ++jj) {
            ull v2 = vptr[jj * 64];
            const ull* prow = (const ull*)&Pd[jj][0];
#pragma unroll
            for (int r = 0; r < 8; ++r) {
                ull p2 = prow[(rg * 8 + r) * 4 + h4];
                asm("fma.rn.f32x2 %0, %1, %2, %0;" : "+l"(acc2[r]) : "l"(p2), "l"(v2));
            }
        }
        __syncthreads();
    }

    // partial softmax denominators
    float s = psum2;
#pragma unroll
    for (int k = 0; k < 8; ++k) s += psum[k];
    ssum[t] = s;
    __syncthreads();
    if (t < 64) {
        float rsp = ssum[t] + ssum[t + 64];        // slot rh = t
        g_psum[((sp * 2 + b) * NN + n0 + (t >> 2)) * 4 + (t & 3)] = rsp;
    }

    // partial AV accumulators
#pragma unroll
    for (int r = 0; r < 8; ++r) {
        int row = n0 + rg * 8 + r;
        ull* dst = (ull*)g_part + (size_t)((sp * 2 + b) * NN + row) * 64 + tp;
        *dst = acc2[r];
    }
}

// ---------------------------------------------------------------------------
// Kernel 3: reduce split partials, normalize, residual, LayerNorm.
// 512 blocks x 128 thr; 8 rows per block, thread = output column.
// ---------------------------------------------------------------------------
__global__ __launch_bounds__(128) void k3_epi(const float* __restrict__ gamma,
                                              const float* __restrict__ beta,
                                              float*       __restrict__ out) {
    const int t  = threadIdx.x;
    const int b  = blockIdx.x >> 8;
    const int n0 = (blockIdx.x & 255) * 8;
    const int h  = t >> 5;
    const int d  = t & 31;

    __shared__ float red1[4][8], red2[4][8];

    const float gma = gamma[t];
    const float bta = beta[t];
    float ys[8];

#pragma unroll
    for (int r = 0; r < 8; ++r) {
        const int n = n0 + r;
        float accv = 0.f, rsum = 0.f;
#pragma unroll
        for (int spp = 0; spp < SPLIT; ++spp) {
            accv += g_part[(size_t)((spp * 2 + b) * NN + n) * 128 + t];
            rsum += g_psum[((spp * 2 + b) * NN + n) * 4 + h];
        }
        float y = accv / rsum + g_h[(b * NN + n) * 128 + t];
        ys[r] = y;
        float s1 = y, s2 = y * y;
#pragma unroll
        for (int off = 16; off; off >>= 1) {
            s1 += __shfl_xor_sync(0xffffffffu, s1, off);
            s2 += __shfl_xor_sync(0xffffffffu, s2, off);
        }
        if (d == 0) { red1[h][r] = s1; red2[h][r] = s2; }
    }
    __syncthreads();
#pragma unroll
    for (int r = 0; r < 8; ++r) {
        float s1 = red1[0][r] + red1[1][r] + red1[2][r] + red1[3][r];
        float s2 = red2[0][r] + red2[1][r] + red2[2][r] + red2[3][r];
        float mu  = s1 * (1.f / 128.f);
        float var = s2 * (1.f / 128.f) - mu * mu;
        float inv = rsqrtf(var + 1e-5f);
        out[(b * NN + n0 + r) * 128 + t] = (ys[r] - mu) * inv * gma + bta;
    }
}

extern "C" void kernel_launch(void* const* d_in, const int* in_sizes, int n_in,
                              void* d_out, int out_size) {
    const float* x     = (const float*)d_in[0];
    const int*   adj   = (const int*)  d_in[1];
    const float* w     = (const float*)d_in[2];
    const float* a     = (const float*)d_in[3];
    const float* gamma = (const float*)d_in[4];
    const float* beta  = (const float*)d_in[5];

    k1_proj<<<512, 128>>>(x, w, a);
    k2_attn<<<2 * 128 * SPLIT, 128>>>(adj);
    k3_epi<<<512, 128>>>(gamma, beta, (float*)d_out);
}

// round 5
// speedup vs baseline: 2.4239x; 1.0301x over previous
#include <cuda_runtime.h>
#include <cuda_bf16.h>

#define NN 2048
#define TN 16
#define TJ 32
#define SPLIT 8
#define JCHUNK (NN / SPLIT)
#define PPITCH 34          // float2 per P row: 272B, 16B-aligned, bank-friendly

typedef unsigned long long ull;

// Scratch (device globals; no allocation allowed)
__device__ float g_h   [2 * NN * 128];          // h[b][n][128]
__device__ float g_v   [2 * NN * 128];          // vperm[b][j][h][d]
__device__ float g_ei  [2 * NN * 4];
__device__ float g_ej  [2 * NN * 4];
__device__ float g_part[SPLIT * 2 * NN * 128];  // partial AV accumulators
__device__ float g_psum[SPLIT * 2 * NN * 4];    // partial softmax denominators

// ---------------------------------------------------------------------------
// Kernel 1: h = x @ w^T, scatter permuted v, compute ei/ej.
// ---------------------------------------------------------------------------
__global__ __launch_bounds__(128) void k1_proj(const float* __restrict__ x,
                                               const float* __restrict__ w,
                                               const float* __restrict__ a) {
    const int t    = threadIdx.x;       // 0..127 = output column (h,d)
    const int r0   = blockIdx.x * 8;
    const int h    = t >> 5;
    const int d    = t & 31;
    const int lane = t & 31;

    __shared__ float ws[128 * 65];
    __shared__ float xs[8 * 64];

#pragma unroll
    for (int k = 0; k < 64; ++k) {
        int idx = t + k * 128;
        ws[(idx >> 6) * 65 + (idx & 63)] = w[idx];
    }
#pragma unroll
    for (int k = 0; k < 4; ++k)
        xs[t + k * 128] = x[r0 * 64 + t + k * 128];
    __syncthreads();

    const float a1v = a[h * 64 + d];
    const float a2v = a[h * 64 + 32 + d];
    const float* wrow = &ws[t * 65];

    for (int rr = 0; rr < 8; ++rr) {
        const int row = r0 + rr;        // = b*NN + n
        float acc = 0.f;
#pragma unroll
        for (int i = 0; i < 64; ++i)
            acc += xs[rr * 64 + i] * wrow[i];

        g_h[row * 128 + t] = acc;

        // vperm scatter: v[b,j,hq,d] = h[b,n,h,d] with j*4+hq = h*NN + n
        const int b   = row >> 11;
        const int n   = row & (NN - 1);
        const int idx = h * NN + n;
        g_v[(b * NN + (idx >> 2)) * 128 + (idx & 3) * 32 + d] = acc;

        float p1 = acc * a1v;
        float p2 = acc * a2v;
#pragma unroll
        for (int off = 16; off; off >>= 1) {
            p1 += __shfl_xor_sync(0xffffffffu, p1, off);
            p2 += __shfl_xor_sync(0xffffffffu, p2, off);
        }
        if (lane == 0) {
            g_ei[row * 4 + h] = p1;
            g_ej[row * 4 + h] = p2;
        }
    }
}

// ---------------------------------------------------------------------------
// Kernel 2: masked-softmax attention, split-j partials.
// Grid: 2048 = B(2) x ntiles(128, TN=16) x SPLIT(8). 128 threads.
// P stage: lane = jj, warp wp covers P-rows wp*16..wp*16+15. Rowsums kept in
// registers across all tiles, butterfly-reduced once at the end.
// AV stage: lane owns 2 column-pairs in one head (c0, c0+8); warp wp owns
// n-rows wp*4..wp*4+3. P stored transposed+duplicated so one LDS.128 feeds
// 4 packed fma.rn.f32x2.
// ---------------------------------------------------------------------------
__global__ __launch_bounds__(128, 8) void k2_attn(const int* __restrict__ adj) {
    const int t    = threadIdx.x;
    const int sp   = blockIdx.x & (SPLIT - 1);
    const int nt   = (blockIdx.x >> 3) & 127;
    const int b    = blockIdx.x >> 10;
    const int n0   = nt * TN;
    const int js   = sp * JCHUNK;
    const int lane = t & 31;
    const int wp   = t >> 5;
    const int h4   = lane >> 3;            // head for AV columns
    const int pq   = lane & 7;
    const int c0   = h4 * 16 + pq;         // ull column indices
    const int c1   = c0 + 8;

    __shared__ float eis[64];                          // [n_row*4+h]
    __shared__ __align__(16) float  ejs[TJ * 4];       // [jj*4+h]
    __shared__ __align__(16) int    adjs[TN * TJ];
    __shared__ __align__(16) float2 Pd[64][PPITCH];    // [row][jj], dup pairs
    __shared__ float rs[64];

    if (t < 64)
        eis[t] = g_ei[(b * NN + n0 + (t >> 2)) * 4 + (t & 3)];

    ull acc[8];
#pragma unroll
    for (int r = 0; r < 8; ++r) acc[r] = 0ull;
    float psum[16];
#pragma unroll
    for (int k = 0; k < 16; ++k) psum[k] = 0.f;

    for (int j0 = js; j0 < js + JCHUNK; j0 += TJ) {
        // stage ej (128 floats) and adj tile (16x32 ints) via 128-bit ops
        ejs[t] = g_ej[(b * NN + j0) * 4 + t];
        {
            int4 a4 = *(const int4*)&adj[(n0 + (t >> 3)) * NN + j0 + (t & 7) * 4];
            *(int4*)&adjs[t * 4] = a4;
        }
        __syncthreads();

        // ---- P stage: thread = (jj=lane), rows wp*16+k ----
        float4 ej4 = *(const float4*)&ejs[lane * 4];
        float adjf[4];
#pragma unroll
        for (int kk = 0; kk < 4; ++kk)
            adjf[kk] = (float)adjs[(wp * 4 + kk) * TJ + lane];
#pragma unroll
        for (int k = 0; k < 16; ++k) {
            int row = wp * 16 + k;
            float ejv = (k & 3) == 0 ? ej4.x : (k & 3) == 1 ? ej4.y
                       : (k & 3) == 2 ? ej4.z : ej4.w;
            float e = eis[row] + ejv;
            e = fmaxf(e, 0.2f * e);                    // leaky relu
            float p = __expf(e) * adjf[k >> 2];        // mask via 0/1 multiply
            psum[k] += p;
            Pd[row][lane] = make_float2(p, p);
        }
        __syncthreads();

        // ---- AV stage: packed f32x2, 1 LDS.128 per 4 FFMA2 ----
        const ull* vrow = (const ull*)g_v + (size_t)(b * NN + j0) * 64;
#pragma unroll
        for (int jj = 0; jj < TJ; jj += 2) {
            ull va0 = vrow[jj * 64 + c0];
            ull vb0 = vrow[jj * 64 + c1];
            ull va1 = vrow[jj * 64 + 64 + c0];
            ull vb1 = vrow[jj * 64 + 64 + c1];
#pragma unroll
            for (int r = 0; r < 4; ++r) {
                ulonglong2 p2 = *(const ulonglong2*)&Pd[wp * 16 + r * 4 + h4][jj];
                asm("fma.rn.f32x2 %0, %1, %2, %0;" : "+l"(acc[r * 2 + 0]) : "l"(p2.x), "l"(va0));
                asm("fma.rn.f32x2 %0, %1, %2, %0;" : "+l"(acc[r * 2 + 1]) : "l"(p2.x), "l"(vb0));
                asm("fma.rn.f32x2 %0, %1, %2, %0;" : "+l"(acc[r * 2 + 0]) : "l"(p2.y), "l"(va1));
                asm("fma.rn.f32x2 %0, %1, %2, %0;" : "+l"(acc[r * 2 + 1]) : "l"(p2.y), "l"(vb1));
            }
        }
        __syncthreads();
    }

    // rowsum: butterfly over lanes (lane = jj slot), once per kernel
#pragma unroll
    for (int k = 0; k < 16; ++k) {
        float s = psum[k];
#pragma unroll
        for (int off = 16; off; off >>= 1)
            s += __shfl_xor_sync(0xffffffffu, s, off);
        if (lane == 0) rs[wp * 16 + k] = s;
    }
    __syncthreads();
    if (t < 64)
        g_psum[((sp * 2 + b) * NN + n0 + (t >> 2)) * 4 + (t & 3)] = rs[t];

    // partial AV accumulators
#pragma unroll
    for (int r = 0; r < 4; ++r) {
        size_t base = (size_t)((sp * 2 + b) * NN + n0 + wp * 4 + r) * 64;
        ((ull*)g_part)[base + c0] = acc[r * 2 + 0];
        ((ull*)g_part)[base + c1] = acc[r * 2 + 1];
    }
}

// ---------------------------------------------------------------------------
// Kernel 3: reduce split partials, normalize, residual, LayerNorm.
// ---------------------------------------------------------------------------
__global__ __launch_bounds__(128) void k3_epi(const float* __restrict__ gamma,
                                              const float* __restrict__ beta,
                                              float*       __restrict__ out) {
    const int t  = threadIdx.x;
    const int b  = blockIdx.x >> 8;
    const int n0 = (blockIdx.x & 255) * 8;
    const int h  = t >> 5;
    const int d  = t & 31;

    __shared__ float red1[4][8], red2[4][8];

    const float gma = gamma[t];
    const float bta = beta[t];
    float ys[8];

#pragma unroll
    for (int r = 0; r < 8; ++r) {
        const int n = n0 + r;
        float accv = 0.f, rsum = 0.f;
#pragma unroll
        for (int spp = 0; spp < SPLIT; ++spp) {
            accv += g_part[(size_t)((spp * 2 + b) * NN + n) * 128 + t];
            rsum += g_psum[((spp * 2 + b) * NN + n) * 4 + h];
        }
        float y = accv / rsum + g_h[(b * NN + n) * 128 + t];
        ys[r] = y;
        float s1 = y, s2 = y * y;
#pragma unroll
        for (int off = 16; off; off >>= 1) {
            s1 += __shfl_xor_sync(0xffffffffu, s1, off);
            s2 += __shfl_xor_sync(0xffffffffu, s2, off);
        }
        if (d == 0) { red1[h][r] = s1; red2[h][r] = s2; }
    }
    __syncthreads();
#pragma unroll
    for (int r = 0; r < 8; ++r) {
        float s1 = red1[0][r] + red1[1][r] + red1[2][r] + red1[3][r];
        float s2 = red2[0][r] + red2[1][r] + red2[2][r] + red2[3][r];
        float mu  = s1 * (1.f / 128.f);
        float var = s2 * (1.f / 128.f) - mu * mu;
        float inv = rsqrtf(var + 1e-5f);
        out[(b * NN + n0 + r) * 128 + t] = (ys[r] - mu) * inv * gma + bta;
    }
}

extern "C" void kernel_launch(void* const* d_in, const int* in_sizes, int n_in,
                              void* d_out, int out_size) {
    const float* x     = (const float*)d_in[0];
    const int*   adj   = (const int*)  d_in[1];
    const float* w     = (const float*)d_in[2];
    const float* a     = (const float*)d_in[3];
    const float* gamma = (const float*)d_in[4];
    const float* beta  = (const float*)d_in[5];

    k1_proj<<<512, 128>>>(x, w, a);
    k2_attn<<<2 * 128 * SPLIT, 128>>>(adj);
    k3_epi<<<512, 128>>>(gamma, beta, (float*)d_out);
}

// round 6
// speedup vs baseline: 2.5632x; 1.0575x over previous
#include <cuda_runtime.h>
#include <cuda_bf16.h>

#define NN 2048
#define TN 16
#define TJ 32
#define SPLIT 16
#define JCHUNK (NN / SPLIT)
#define PPITCH 34          // float2 per P row: 272B, LDS.128-aligned at even jj

typedef unsigned long long ull;

// Scratch (device globals; no allocation allowed)
__device__ float g_h   [2 * NN * 128];          // h[b][n][128]
__device__ float g_v   [2 * NN * 128];          // vperm[b][j][h][d]
__device__ float g_ei  [2 * NN * 4];
__device__ float g_ej  [2 * NN * 4];
__device__ float g_part[SPLIT * 2 * NN * 128];  // partial AV accumulators
__device__ float g_psum[SPLIT * 2 * NN * 4];    // partial softmax denominators

// ---------------------------------------------------------------------------
// Kernel 1: h = x @ w^T, scatter permuted v, compute ei/ej.
// ---------------------------------------------------------------------------
__global__ __launch_bounds__(128) void k1_proj(const float* __restrict__ x,
                                               const float* __restrict__ w,
                                               const float* __restrict__ a) {
    const int t    = threadIdx.x;       // 0..127 = output column (h,d)
    const int r0   = blockIdx.x * 8;
    const int h    = t >> 5;
    const int d    = t & 31;
    const int lane = t & 31;

    __shared__ float ws[128 * 65];
    __shared__ float xs[8 * 64];

#pragma unroll
    for (int k = 0; k < 64; ++k) {
        int idx = t + k * 128;
        ws[(idx >> 6) * 65 + (idx & 63)] = w[idx];
    }
#pragma unroll
    for (int k = 0; k < 4; ++k)
        xs[t + k * 128] = x[r0 * 64 + t + k * 128];
    __syncthreads();

    const float a1v = a[h * 64 + d];
    const float a2v = a[h * 64 + 32 + d];
    const float* wrow = &ws[t * 65];

    for (int rr = 0; rr < 8; ++rr) {
        const int row = r0 + rr;        // = b*NN + n
        float acc = 0.f;
#pragma unroll
        for (int i = 0; i < 64; ++i)
            acc += xs[rr * 64 + i] * wrow[i];

        g_h[row * 128 + t] = acc;

        // vperm scatter: v[b,j,hq,d] = h[b,n,h,d] with j*4+hq = h*NN + n
        const int b   = row >> 11;
        const int n   = row & (NN - 1);
        const int idx = h * NN + n;
        g_v[(b * NN + (idx >> 2)) * 128 + (idx & 3) * 32 + d] = acc;

        float p1 = acc * a1v;
        float p2 = acc * a2v;
#pragma unroll
        for (int off = 16; off; off >>= 1) {
            p1 += __shfl_xor_sync(0xffffffffu, p1, off);
            p2 += __shfl_xor_sync(0xffffffffu, p2, off);
        }
        if (lane == 0) {
            g_ei[row * 4 + h] = p1;
            g_ej[row * 4 + h] = p2;
        }
    }
}

// ---------------------------------------------------------------------------
// Kernel 2: masked-softmax attention, split-j partials.
// Grid: 4096 = B(2) x ntiles(128, TN=16) x SPLIT(16). 128 threads.
// V tile staged to smem via cp.async (overlapped with P stage).
// P stage: lane = jj, warp wp covers P-rows wp*16..wp*16+15 (rowsums in regs).
// AV stage: thread = (col-pair cp = t&63, row-group rg = t>>6); v from smem
// LDS.64 (contiguous, conflict-free), P via broadcast LDS.128 of duplicated
// pairs; fma.rn.f32x2 throughout.
// ---------------------------------------------------------------------------
__global__ __launch_bounds__(128, 6) void k2_attn(const int* __restrict__ adj) {
    const int t    = threadIdx.x;
    const int sp   = blockIdx.x & (SPLIT - 1);
    const int nt   = (blockIdx.x >> 4) & 127;
    const int b    = blockIdx.x >> 11;
    const int n0   = nt * TN;
    const int js   = sp * JCHUNK;
    const int lane = t & 31;
    const int wp   = t >> 5;
    const int cp   = t & 63;               // ull column pair (float cols 2cp,2cp+1)
    const int rg   = t >> 6;               // row group: n-rows rg*8..rg*8+7
    const int h4   = cp >> 4;              // head of this column

    __shared__ float eis[64];                          // [n_row*4+h]
    __shared__ __align__(16) float  ejs[TJ * 4];       // [jj*4+h]
    __shared__ __align__(16) int    adjs[TN * TJ];
    __shared__ __align__(16) float2 Pd[64][PPITCH];    // [slot][jj], dup pairs
    __shared__ __align__(16) float  vsm[TJ * 128];     // staged v tile (16KB)
    __shared__ float rs[64];

    if (t < 64)
        eis[t] = g_ei[(b * NN + n0 + (t >> 2)) * 4 + (t & 3)];

    ull acc[8];
#pragma unroll
    for (int r = 0; r < 8; ++r) acc[r] = 0ull;
    float psum[16];
#pragma unroll
    for (int k = 0; k < 16; ++k) psum[k] = 0.f;

    const unsigned vsm_base = (unsigned)__cvta_generic_to_shared(vsm);

    for (int j0 = js; j0 < js + JCHUNK; j0 += TJ) {
        // kick off async V tile copy (16KB): 8 x 16B per thread
        {
            const float* vsrc = g_v + (size_t)(b * NN + j0) * 128;
#pragma unroll
            for (int k = 0; k < 8; ++k) {
                unsigned dst = vsm_base + (t + k * 128) * 16;
                const float4* src = (const float4*)vsrc + t + k * 128;
                asm volatile("cp.async.cg.shared.global [%0], [%1], 16;"
                             :: "r"(dst), "l"(src));
            }
            asm volatile("cp.async.commit_group;");
        }
        // stage ej (128 floats) and adj tile (16x32 ints)
        ejs[t] = g_ej[(b * NN + j0) * 4 + t];
        {
            int4 a4 = *(const int4*)&adj[(n0 + (t >> 3)) * NN + j0 + (t & 7) * 4];
            *(int4*)&adjs[t * 4] = a4;
        }
        __syncthreads();

        // ---- P stage: thread = (jj=lane), rows wp*16+k ----
        float4 ej4 = *(const float4*)&ejs[lane * 4];
        float adjf[4];
#pragma unroll
        for (int kk = 0; kk < 4; ++kk)
            adjf[kk] = (float)adjs[(wp * 4 + kk) * TJ + lane];
#pragma unroll
        for (int k = 0; k < 16; ++k) {
            int row = wp * 16 + k;
            float ejv = (k & 3) == 0 ? ej4.x : (k & 3) == 1 ? ej4.y
                       : (k & 3) == 2 ? ej4.z : ej4.w;
            float e = eis[row] + ejv;
            e = fmaxf(e, 0.2f * e);                    // leaky relu
            float p = __expf(e) * adjf[k >> 2];        // mask via 0/1 multiply
            psum[k] += p;
            Pd[row][lane] = make_float2(p, p);
        }
        asm volatile("cp.async.wait_group 0;");
        __syncthreads();

        // ---- AV stage: v from smem, P broadcast LDS.128, packed f32x2 ----
#pragma unroll
        for (int jj = 0; jj < TJ; jj += 2) {
            ull v0 = *(const ull*)&vsm[jj * 128 + cp * 2];
            ull v1 = *(const ull*)&vsm[jj * 128 + 128 + cp * 2];
#pragma unroll
            for (int r = 0; r < 8; ++r) {
                ulonglong2 p2 = *(const ulonglong2*)&Pd[(rg * 8 + r) * 4 + h4][jj];
                asm("fma.rn.f32x2 %0, %1, %2, %0;" : "+l"(acc[r]) : "l"(p2.x), "l"(v0));
                asm("fma.rn.f32x2 %0, %1, %2, %0;" : "+l"(acc[r]) : "l"(p2.y), "l"(v1));
            }
        }
        __syncthreads();
    }

    // rowsum: butterfly over lanes (lane = jj slot), once per kernel
#pragma unroll
    for (int k = 0; k < 16; ++k) {
        float s = psum[k];
#pragma unroll
        for (int off = 16; off; off >>= 1)
            s += __shfl_xor_sync(0xffffffffu, s, off);
        if (lane == 0) rs[wp * 16 + k] = s;
    }
    __syncthreads();
    if (t < 64)
        g_psum[((sp * 2 + b) * NN + n0 + (t >> 2)) * 4 + (t & 3)] = rs[t];

    // partial AV accumulators: row n0+rg*8+r, ull col cp
#pragma unroll
    for (int r = 0; r < 8; ++r) {
        size_t base = (size_t)((sp * 2 + b) * NN + n0 + rg * 8 + r) * 64;
        ((ull*)g_part)[base + cp] = acc[r];
    }
}

// ---------------------------------------------------------------------------
// Kernel 3: reduce split partials, normalize, residual, LayerNorm.
// ---------------------------------------------------------------------------
__global__ __launch_bounds__(128) void k3_epi(const float* __restrict__ gamma,
                                              const float* __restrict__ beta,
                                              float*       __restrict__ out) {
    const int t  = threadIdx.x;
    const int b  = blockIdx.x >> 8;
    const int n0 = (blockIdx.x & 255) * 8;
    const int h  = t >> 5;
    const int d  = t & 31;

    __shared__ float red1[4][8], red2[4][8];

    const float gma = gamma[t];
    const float bta = beta[t];
    float ys[8];

#pragma unroll
    for (int r = 0; r < 8; ++r) {
        const int n = n0 + r;
        float accv = 0.f, rsum = 0.f;
#pragma unroll
        for (int spp = 0; spp < SPLIT; ++spp) {
            accv += g_part[(size_t)((spp * 2 + b) * NN + n) * 128 + t];
            rsum += g_psum[((spp * 2 + b) * NN + n) * 4 + h];
        }
        float y = accv / rsum + g_h[(b * NN + n) * 128 + t];
        ys[r] = y;
        float s1 = y, s2 = y * y;
#pragma unroll
        for (int off = 16; off; off >>= 1) {
            s1 += __shfl_xor_sync(0xffffffffu, s1, off);
            s2 += __shfl_xor_sync(0xffffffffu, s2, off);
        }
        if (d == 0) { red1[h][r] = s1; red2[h][r] = s2; }
    }
    __syncthreads();
#pragma unroll
    for (int r = 0; r < 8; ++r) {
        float s1 = red1[0][r] + red1[1][r] + red1[2][r] + red1[3][r];
        float s2 = red2[0][r] + red2[1][r] + red2[2][r] + red2[3][r];
        float mu  = s1 * (1.f / 128.f);
        float var = s2 * (1.f / 128.f) - mu * mu;
        float inv = rsqrtf(var + 1e-5f);
        out[(b * NN + n0 + r) * 128 + t] = (ys[r] - mu) * inv * gma + bta;
    }
}

extern "C" void kernel_launch(void* const* d_in, const int* in_sizes, int n_in,
                              void* d_out, int out_size) {
    const float* x     = (const float*)d_in[0];
    const int*   adj   = (const int*)  d_in[1];
    const float* w     = (const float*)d_in[2];
    const float* a     = (const float*)d_in[3];
    const float* gamma = (const float*)d_in[4];
    const float* beta  = (const float*)d_in[5];

    k1_proj<<<512, 128>>>(x, w, a);
    k2_attn<<<2 * 128 * SPLIT, 128>>>(adj);
    k3_epi<<<512, 128>>>(gamma, beta, (float*)d_out);
}

// round 9
// speedup vs baseline: 3.8049x; 1.4845x over previous
#include <cuda_runtime.h>
#include <cuda_bf16.h>
#include <cstdint>

#define NN 2048
#define TJ 32
#define SPLIT 16
#define JCHUNK (NN / SPLIT)      // 128
#define NTILES (JCHUNK / TJ)     // 4

typedef unsigned long long ull;

// Scratch (device globals; no allocation allowed)
__device__ float g_h   [2 * NN * 128];          // h[b][n][128]
__device__ float g_v   [2 * NN * 128];          // vperm[b][j][h*32+d], tf32-rounded
__device__ float g_ei  [2 * NN * 4];
__device__ float g_ej  [2 * NN * 4];
__device__ float g_part[SPLIT * 2 * NN * 128];  // partial AV accumulators
__device__ float g_psum[SPLIT * 2 * NN * 4];    // partial softmax denominators

__device__ __forceinline__ float tf32r(float x) {
    uint32_t u;
    asm("cvt.rna.tf32.f32 %0, %1;" : "=r"(u) : "f"(x));
    return __uint_as_float(u);
}

// ---------------------------------------------------------------------------
// Kernel 1: h = x @ w^T, scatter permuted v (tf32-rounded), compute ei/ej.
// ---------------------------------------------------------------------------
__global__ __launch_bounds__(128) void k1_proj(const float* __restrict__ x,
                                               const float* __restrict__ w,
                                               const float* __restrict__ a) {
    const int t    = threadIdx.x;
    const int r0   = blockIdx.x * 8;
    const int h    = t >> 5;
    const int d    = t & 31;
    const int lane = t & 31;

    __shared__ float ws[128 * 65];
    __shared__ float xs[8 * 64];

#pragma unroll
    for (int k = 0; k < 64; ++k) {
        int idx = t + k * 128;
        ws[(idx >> 6) * 65 + (idx & 63)] = w[idx];
    }
#pragma unroll
    for (int k = 0; k < 4; ++k)
        xs[t + k * 128] = x[r0 * 64 + t + k * 128];
    __syncthreads();

    const float a1v = a[h * 64 + d];
    const float a2v = a[h * 64 + 32 + d];
    const float* wrow = &ws[t * 65];

    for (int rr = 0; rr < 8; ++rr) {
        const int row = r0 + rr;
        float acc = 0.f;
#pragma unroll
        for (int i = 0; i < 64; ++i)
            acc += xs[rr * 64 + i] * wrow[i];

        g_h[row * 128 + t] = acc;

        const int b   = row >> 11;
        const int n   = row & (NN - 1);
        const int idx = h * NN + n;
        g_v[(b * NN + (idx >> 2)) * 128 + (idx & 3) * 32 + d] = tf32r(acc);

        float p1 = acc * a1v;
        float p2 = acc * a2v;
#pragma unroll
        for (int off = 16; off; off >>= 1) {
            p1 += __shfl_xor_sync(0xffffffffu, p1, off);
            p2 += __shfl_xor_sync(0xffffffffu, p2, off);
        }
        if (lane == 0) {
            g_ei[row * 4 + h] = p1;
            g_ej[row * 4 + h] = p2;
        }
    }
}

// ---------------------------------------------------------------------------
// Kernel 2: attention via tf32 mma.sync.m16n8k8. Grid 512 = sp(16) x nt(16)
// x b(2); 256 threads = 8 warps x 16 rows. P computed directly into A-frags
// (never touches smem); V + adj mask staged via cp.async; accumulators in
// registers across the whole JCHUNK; fp32 accumulate.
//
// m16n8k8 frag maps (lane = qr*4+qc, qr=lane/4, qc=lane%4):
//   A: a0=(qr, qc) a1=(qr+8, qc) a2=(qr, qc+4) a3=(qr+8, qc+4)   [row, k]
//   B: b0=(qc, qr) b1=(qc+4, qr)                                  [k, col]
//   C: c0=(qr, 2qc) c1=(qr, 2qc+1) c2=(qr+8, 2qc) c3=(qr+8, 2qc+1)
// ---------------------------------------------------------------------------
__global__ __launch_bounds__(256, 2) void k2_attn(const int* __restrict__ adj) {
    const int t  = threadIdx.x;
    const int wp = t >> 5;
    const int qr = (t & 31) >> 2;
    const int qc = t & 3;
    const int sp = blockIdx.x & 15;
    const int nt = (blockIdx.x >> 4) & 15;
    const int b  = blockIdx.x >> 8;
    const int n0 = nt * 128;
    const int js = sp * JCHUNK;
    const int r0 = wp * 16;                 // warp's row base within tile

    __shared__ __align__(16) float vsm[TJ][136];   // padded: conflict-free B-frag LDS
    __shared__ __align__(16) int   msm[128][36];   // padded: conflict-free mask LDS
    __shared__ __align__(16) float ejs[TJ][4];

    // ei for this lane's two frag rows, all 4 heads
    const float4 eiA = *(const float4*)&g_ei[(size_t)(b * NN + n0 + r0 + qr) * 4];
    const float4 eiB = *(const float4*)&g_ei[(size_t)(b * NN + n0 + r0 + 8 + qr) * 4];

    float acc[16][4];                       // [h*4+n][c0..c3]
#pragma unroll
    for (int i = 0; i < 16; ++i)
#pragma unroll
        for (int j = 0; j < 4; ++j) acc[i][j] = 0.f;
    float ps0[4], ps1[4];                   // psum for rows qr / qr+8, per head
#pragma unroll
    for (int h = 0; h < 4; ++h) { ps0[h] = 0.f; ps1[h] = 0.f; }

    uint32_t vbase, mbase;
    asm("{ .reg .u64 u; cvta.to.shared.u64 u, %1; cvt.u32.u64 %0, u; }" : "=r"(vbase) : "l"(vsm));
    asm("{ .reg .u64 u; cvta.to.shared.u64 u, %1; cvt.u32.u64 %0, u; }" : "=r"(mbase) : "l"(msm));

    for (int tile = 0; tile < NTILES; ++tile) {
        const int j0 = js + tile * TJ;
        __syncthreads();
        // V tile: 32 rows x 512B -> smem pitch 544B (16B-aligned)
#pragma unroll
        for (int k = 0; k < 4; ++k) {
            int c = t + k * 256;
            int row = c >> 5, o = c & 31;
            uint32_t dst = vbase + row * 544 + o * 16;
            const float* src = g_v + (size_t)(b * NN + j0 + row) * 128 + o * 4;
            asm volatile("cp.async.cg.shared.global [%0], [%1], 16;" :: "r"(dst), "l"(src));
        }
        // mask tile: 128 rows x 128B -> smem pitch 144B
#pragma unroll
        for (int k = 0; k < 4; ++k) {
            int c = t + k * 256;
            int row = c >> 3, o = c & 7;
            uint32_t dst = mbase + row * 144 + o * 16;
            const int* src = adj + (size_t)(n0 + row) * NN + j0 + o * 4;
            asm volatile("cp.async.cg.shared.global [%0], [%1], 16;" :: "r"(dst), "l"(src));
        }
        if (t < TJ)
            *(float4*)&ejs[t][0] = *(const float4*)&g_ej[(size_t)(b * NN + j0 + t) * 4];
        asm volatile("cp.async.commit_group;");
        asm volatile("cp.async.wait_group 0;" ::: "memory");
        __syncthreads();

#pragma unroll
        for (int ks = 0; ks < 4; ++ks) {
            const int jc = ks * 8 + qc;
            const int m0 = msm[r0 + qr][jc];
            const int m1 = msm[r0 + 8 + qr][jc];
            const int m2 = msm[r0 + qr][jc + 4];
            const int m3 = msm[r0 + 8 + qr][jc + 4];
            const float4 ejA = *(const float4*)&ejs[jc][0];
            const float4 ejB = *(const float4*)&ejs[jc + 4][0];
#pragma unroll
            for (int h = 0; h < 4; ++h) {
                const float ei0 = (&eiA.x)[h], ei1 = (&eiB.x)[h];
                const float ej0 = (&ejA.x)[h], ej1 = (&ejB.x)[h];
                float e, p;
                uint32_t a0, a1, a2, a3;
                e = ei0 + ej0; e = fmaxf(e, 0.2f * e);
                p = m0 ? tf32r(__expf(e)) : 0.f; ps0[h] += p; a0 = __float_as_uint(p);
                e = ei1 + ej0; e = fmaxf(e, 0.2f * e);
                p = m1 ? tf32r(__expf(e)) : 0.f; ps1[h] += p; a1 = __float_as_uint(p);
                e = ei0 + ej1; e = fmaxf(e, 0.2f * e);
                p = m2 ? tf32r(__expf(e)) : 0.f; ps0[h] += p; a2 = __float_as_uint(p);
                e = ei1 + ej1; e = fmaxf(e, 0.2f * e);
                p = m3 ? tf32r(__expf(e)) : 0.f; ps1[h] += p; a3 = __float_as_uint(p);
#pragma unroll
                for (int n = 0; n < 4; ++n) {
                    const int col = h * 32 + n * 8 + qr;
                    uint32_t b0 = __float_as_uint(vsm[jc][col]);
                    uint32_t b1 = __float_as_uint(vsm[jc + 4][col]);
                    float* c = acc[h * 4 + n];
                    asm("mma.sync.aligned.m16n8k8.row.col.f32.tf32.tf32.f32 "
                        "{%0,%1,%2,%3}, {%4,%5,%6,%7}, {%8,%9}, {%0,%1,%2,%3};"
                        : "+f"(c[0]), "+f"(c[1]), "+f"(c[2]), "+f"(c[3])
                        : "r"(a0), "r"(a1), "r"(a2), "r"(a3), "r"(b0), "r"(b1));
                }
            }
        }
    }

    // psum: reduce over qc (lanes covering disjoint j), write rowsums
#pragma unroll
    for (int h = 0; h < 4; ++h) {
        ps0[h] += __shfl_xor_sync(0xffffffffu, ps0[h], 1);
        ps0[h] += __shfl_xor_sync(0xffffffffu, ps0[h], 2);
        ps1[h] += __shfl_xor_sync(0xffffffffu, ps1[h], 1);
        ps1[h] += __shfl_xor_sync(0xffffffffu, ps1[h], 2);
    }
    if (qc == 0) {
        size_t base = ((size_t)(sp * 2 + b) * NN + n0 + r0);
        *(float4*)&g_psum[(base + qr) * 4]     = make_float4(ps0[0], ps0[1], ps0[2], ps0[3]);
        *(float4*)&g_psum[(base + 8 + qr) * 4] = make_float4(ps1[0], ps1[1], ps1[2], ps1[3]);
    }

    // accumulator writeback: float2 per frag row
    {
        size_t base0 = ((size_t)(sp * 2 + b) * NN + n0 + r0 + qr) * 128;
        size_t base1 = base0 + 8 * 128;
#pragma unroll
        for (int h = 0; h < 4; ++h)
#pragma unroll
            for (int n = 0; n < 4; ++n) {
                const int col = h * 32 + n * 8 + qc * 2;
                const float* c = acc[h * 4 + n];
                *(float2*)&g_part[base0 + col] = make_float2(c[0], c[1]);
                *(float2*)&g_part[base1 + col] = make_float2(c[2], c[3]);
            }
    }
}

// ---------------------------------------------------------------------------
// Kernel 3: reduce split partials, normalize, residual, LayerNorm.
// ---------------------------------------------------------------------------
__global__ __launch_bounds__(128) void k3_epi(const float* __restrict__ gamma,
                                              const float* __restrict__ beta,
                                              float*       __restrict__ out) {
    const int t  = threadIdx.x;
    const int b  = blockIdx.x >> 8;
    const int n0 = (blockIdx.x & 255) * 8;
    const int h  = t >> 5;
    const int d  = t & 31;

    __shared__ float red1[4][8], red2[4][8];

    const float gma = gamma[t];
    const float bta = beta[t];
    float ys[8];

#pragma unroll
    for (int r = 0; r < 8; ++r) {
        const int n = n0 + r;
        float accv = 0.f, rsum = 0.f;
#pragma unroll
        for (int spp = 0; spp < SPLIT; ++spp) {
            accv += g_part[(size_t)((spp * 2 + b) * NN + n) * 128 + t];
            rsum += g_psum[((size_t)(spp * 2 + b) * NN + n) * 4 + h];
        }
        float y = accv / rsum + g_h[(size_t)(b * NN + n) * 128 + t];
        ys[r] = y;
        float s1 = y, s2 = y * y;
#pragma unroll
        for (int off = 16; off; off >>= 1) {
            s1 += __shfl_xor_sync(0xffffffffu, s1, off);
            s2 += __shfl_xor_sync(0xffffffffu, s2, off);
        }
        if (d == 0) { red1[h][r] = s1; red2[h][r] = s2; }
    }
    __syncthreads();
#pragma unroll
    for (int r = 0; r < 8; ++r) {
        float s1 = red1[0][r] + red1[1][r] + red1[2][r] + red1[3][r];
        float s2 = red2[0][r] + red2[1][r] + red2[2][r] + red2[3][r];
        float mu  = s1 * (1.f / 128.f);
        float var = s2 * (1.f / 128.f) - mu * mu;
        float inv = rsqrtf(var + 1e-5f);
        out[(size_t)(b * NN + n0 + r) * 128 + t] = (ys[r] - mu) * inv * gma + bta;
    }
}

extern "C" void kernel_launch(void* const* d_in, const int* in_sizes, int n_in,
                              void* d_out, int out_size) {
    const float* x     = (const float*)d_in[0];
    const int*   adj   = (const int*)  d_in[1];
    const float* w     = (const float*)d_in[2];
    const float* a     = (const float*)d_in[3];
    const float* gamma = (const float*)d_in[4];
    const float* beta  = (const float*)d_in[5];

    k1_proj<<<512, 128>>>(x, w, a);
    k2_attn<<<512, 256>>>(adj);
    k3_epi<<<512, 128>>>(gamma, beta, (float*)d_out);
}

// round 11
// speedup vs baseline: 4.4306x; 1.1645x over previous
#include <cuda_runtime.h>
#include <cuda_bf16.h>
#include <cstdint>

#define NN 2048
#define TJ 32
#define SPLIT 8
#define JCHUNK (NN / SPLIT)      // 256
#define NTILES (JCHUNK / TJ)     // 8

typedef unsigned long long ull;

// Scratch (device globals; no allocation allowed)
__device__ float g_h   [2 * NN * 128];          // h[b][n][128]
__device__ float g_v   [2 * NN * 128];          // vperm[b][j][h*32+d], tf32-rounded
__device__ float g_ei  [2 * NN * 4];
__device__ float g_ej  [2 * NN * 4];
__device__ float g_part[SPLIT * 2 * NN * 128];  // partial AV accumulators
__device__ float g_psum[SPLIT * 2 * NN * 4];    // partial softmax denominators

__device__ __forceinline__ float tf32r(float x) {
    uint32_t u;
    asm("cvt.rna.tf32.f32 %0, %1;" : "=r"(u) : "f"(x));
    return __uint_as_float(u);
}

// dynamic smem layout (bytes):
//   vsm: 2 bufs x 32 x 136 floats  -> 0      .. 34816
//   msm: 2 bufs x 128 x 36 ints    -> 34816  .. 71680
//   ejs: 2 bufs x 32 x 4 floats    -> 71680  .. 72704
#define VSM_OFF 0
#define VSM_BUF (TJ * 136 * 4)          // 17408
#define MSM_OFF (2 * VSM_BUF)           // 34816
#define MSM_BUF (128 * 36 * 4)          // 18432
#define EJS_OFF (MSM_OFF + 2 * MSM_BUF) // 71680
#define EJS_BUF (TJ * 4 * 4)            // 512
#define SMEM_SZ (EJS_OFF + 2 * EJS_BUF) // 72704

// ---------------------------------------------------------------------------
// Kernel 1: h = x @ w^T, scatter permuted v (tf32-rounded), compute ei/ej.
// ---------------------------------------------------------------------------
__global__ __launch_bounds__(128) void k1_proj(const float* __restrict__ x,
                                               const float* __restrict__ w,
                                               const float* __restrict__ a) {
    const int t    = threadIdx.x;
    const int r0   = blockIdx.x * 8;
    const int h    = t >> 5;
    const int d    = t & 31;
    const int lane = t & 31;

    __shared__ float ws[128 * 65];
    __shared__ float xs[8 * 64];

#pragma unroll
    for (int k = 0; k < 64; ++k) {
        int idx = t + k * 128;
        ws[(idx >> 6) * 65 + (idx & 63)] = w[idx];
    }
#pragma unroll
    for (int k = 0; k < 4; ++k)
        xs[t + k * 128] = x[r0 * 64 + t + k * 128];
    __syncthreads();

    const float a1v = a[h * 64 + d];
    const float a2v = a[h * 64 + 32 + d];
    const float* wrow = &ws[t * 65];

    for (int rr = 0; rr < 8; ++rr) {
        const int row = r0 + rr;
        float acc = 0.f;
#pragma unroll
        for (int i = 0; i < 64; ++i)
            acc += xs[rr * 64 + i] * wrow[i];

        g_h[row * 128 + t] = acc;

        const int b   = row >> 11;
        const int n   = row & (NN - 1);
        const int idx = h * NN + n;
        g_v[(b * NN + (idx >> 2)) * 128 + (idx & 3) * 32 + d] = tf32r(acc);

        float p1 = acc * a1v;
        float p2 = acc * a2v;
#pragma unroll
        for (int off = 16; off; off >>= 1) {
            p1 += __shfl_xor_sync(0xffffffffu, p1, off);
            p2 += __shfl_xor_sync(0xffffffffu, p2, off);
        }
        if (lane == 0) {
            g_ei[row * 4 + h] = p1;
            g_ej[row * 4 + h] = p2;
        }
    }
}

// ---------------------------------------------------------------------------
// Kernel 2: attention via tf32 mma.sync.m16n8k8, double-buffered cp.async.
// Grid 256 = sp(8) x nt(16) x b(2) -> exactly one wave at 2 CTAs/SM.
// 256 threads = 8 warps x 16 rows. P computed directly into A-frags;
// V + adj mask prefetched one tile ahead (dynamic smem); 64 fp32
// accumulators per thread persist across the whole 256-j chunk.
// ---------------------------------------------------------------------------
__global__ __launch_bounds__(256, 2) void k2_attn(const int* __restrict__ adj) {
    extern __shared__ __align__(16) char smem[];
    const int t  = threadIdx.x;
    const int wp = t >> 5;
    const int qr = (t & 31) >> 2;
    const int qc = t & 3;
    const int sp = blockIdx.x & 7;
    const int nt = (blockIdx.x >> 3) & 15;
    const int b  = blockIdx.x >> 7;
    const int n0 = nt * 128;
    const int js = sp * JCHUNK;
    const int r0 = wp * 16;                 // warp's row base within tile

    const float4 eiA = *(const float4*)&g_ei[(size_t)(b * NN + n0 + r0 + qr) * 4];
    const float4 eiB = *(const float4*)&g_ei[(size_t)(b * NN + n0 + r0 + 8 + qr) * 4];

    float acc[16][4];
#pragma unroll
    for (int i = 0; i < 16; ++i)
#pragma unroll
        for (int j = 0; j < 4; ++j) acc[i][j] = 0.f;
    float ps0[4], ps1[4];
#pragma unroll
    for (int h = 0; h < 4; ++h) { ps0[h] = 0.f; ps1[h] = 0.f; }

    uint32_t sbase;
    asm("{ .reg .u64 u; cvta.to.shared.u64 u, %1; cvt.u32.u64 %0, u; }" : "=r"(sbase) : "l"(smem));

    // tile loader: issues cp.async for tile index `tile` into buffer tile&1
    auto issue = [&](int tile) {
        const int j0  = js + tile * TJ;
        const int buf = tile & 1;
        const uint32_t vbase = sbase + VSM_OFF + buf * VSM_BUF;
        const uint32_t mbase = sbase + MSM_OFF + buf * MSM_BUF;
#pragma unroll
        for (int k = 0; k < 4; ++k) {
            int c = t + k * 256;
            int row = c >> 5, o = c & 31;
            uint32_t dst = vbase + row * 544 + o * 16;
            const float* src = g_v + (size_t)(b * NN + j0 + row) * 128 + o * 4;
            asm volatile("cp.async.cg.shared.global [%0], [%1], 16;" :: "r"(dst), "l"(src));
        }
#pragma unroll
        for (int k = 0; k < 4; ++k) {
            int c = t + k * 256;
            int row = c >> 3, o = c & 7;
            uint32_t dst = mbase + row * 144 + o * 16;
            const int* src = adj + (size_t)(n0 + row) * NN + j0 + o * 4;
            asm volatile("cp.async.cg.shared.global [%0], [%1], 16;" :: "r"(dst), "l"(src));
        }
        if (t < TJ)
            *(float4*)(smem + EJS_OFF + buf * EJS_BUF + t * 16)
                = *(const float4*)&g_ej[(size_t)(b * NN + j0 + t) * 4];
        asm volatile("cp.async.commit_group;");
    };

    issue(0);

    for (int tile = 0; tile < NTILES; ++tile) {
        const int buf = tile & 1;
        const float* vsm = (const float*)(smem + VSM_OFF + buf * VSM_BUF);
        const int*   msm = (const int*)  (smem + MSM_OFF + buf * MSM_BUF);
        const float* ejs = (const float*)(smem + EJS_OFF + buf * EJS_BUF);

        if (tile + 1 < NTILES) {
            issue(tile + 1);
            asm volatile("cp.async.wait_group 1;" ::: "memory");
        } else {
            asm volatile("cp.async.wait_group 0;" ::: "memory");
        }
        __syncthreads();

#pragma unroll
        for (int ks = 0; ks < 4; ++ks) {
            const int jc = ks * 8 + qc;
            const int m0 = msm[(r0 + qr) * 36 + jc];
            const int m1 = msm[(r0 + 8 + qr) * 36 + jc];
            const int m2 = msm[(r0 + qr) * 36 + jc + 4];
            const int m3 = msm[(r0 + 8 + qr) * 36 + jc + 4];
            const float4 ejA = *(const float4*)&ejs[jc * 4];
            const float4 ejB = *(const float4*)&ejs[(jc + 4) * 4];
#pragma unroll
            for (int h = 0; h < 4; ++h) {
                const float ei0 = (&eiA.x)[h], ei1 = (&eiB.x)[h];
                const float ej0 = (&ejA.x)[h], ej1 = (&ejB.x)[h];
                float e, p;
                uint32_t a0, a1, a2, a3;
                e = ei0 + ej0; e = fmaxf(e, 0.2f * e);
                p = m0 ? tf32r(__expf(e)) : 0.f; ps0[h] += p; a0 = __float_as_uint(p);
                e = ei1 + ej0; e = fmaxf(e, 0.2f * e);
                p = m1 ? tf32r(__expf(e)) : 0.f; ps1[h] += p; a1 = __float_as_uint(p);
                e = ei0 + ej1; e = fmaxf(e, 0.2f * e);
                p = m2 ? tf32r(__expf(e)) : 0.f; ps0[h] += p; a2 = __float_as_uint(p);
                e = ei1 + ej1; e = fmaxf(e, 0.2f * e);
                p = m3 ? tf32r(__expf(e)) : 0.f; ps1[h] += p; a3 = __float_as_uint(p);
#pragma unroll
                for (int n = 0; n < 4; ++n) {
                    const int col = h * 32 + n * 8 + qr;
                    uint32_t b0 = __float_as_uint(vsm[jc * 136 + col]);
                    uint32_t b1 = __float_as_uint(vsm[(jc + 4) * 136 + col]);
                    float* c = acc[h * 4 + n];
                    asm("mma.sync.aligned.m16n8k8.row.col.f32.tf32.tf32.f32 "
                        "{%0,%1,%2,%3}, {%4,%5,%6,%7}, {%8,%9}, {%0,%1,%2,%3};"
                        : "+f"(c[0]), "+f"(c[1]), "+f"(c[2]), "+f"(c[3])
                        : "r"(a0), "r"(a1), "r"(a2), "r"(a3), "r"(b0), "r"(b1));
                }
            }
        }
        __syncthreads();   // buffer tile&1 free for reuse by issue(tile+2)
    }

    // psum: reduce over qc (lanes covering disjoint j)
#pragma unroll
    for (int h = 0; h < 4; ++h) {
        ps0[h] += __shfl_xor_sync(0xffffffffu, ps0[h], 1);
        ps0[h] += __shfl_xor_sync(0xffffffffu, ps0[h], 2);
        ps1[h] += __shfl_xor_sync(0xffffffffu, ps1[h], 1);
        ps1[h] += __shfl_xor_sync(0xffffffffu, ps1[h], 2);
    }
    if (qc == 0) {
        size_t base = ((size_t)(sp * 2 + b) * NN + n0 + r0);
        *(float4*)&g_psum[(base + qr) * 4]     = make_float4(ps0[0], ps0[1], ps0[2], ps0[3]);
        *(float4*)&g_psum[(base + 8 + qr) * 4] = make_float4(ps1[0], ps1[1], ps1[2], ps1[3]);
    }

    // accumulator writeback
    {
        size_t base0 = ((size_t)(sp * 2 + b) * NN + n0 + r0 + qr) * 128;
        size_t base1 = base0 + 8 * 128;
#pragma unroll
        for (int h = 0; h < 4; ++h)
#pragma unroll
            for (int n = 0; n < 4; ++n) {
                const int col = h * 32 + n * 8 + qc * 2;
                const float* c = acc[h * 4 + n];
                *(float2*)&g_part[base0 + col] = make_float2(c[0], c[1]);
                *(float2*)&g_part[base1 + col] = make_float2(c[2], c[3]);
            }
    }
}

// ---------------------------------------------------------------------------
// Kernel 3: reduce split partials, normalize, residual, LayerNorm.
// ---------------------------------------------------------------------------
__global__ __launch_bounds__(128) void k3_epi(const float* __restrict__ gamma,
                                              const float* __restrict__ beta,
                                              float*       __restrict__ out) {
    const int t  = threadIdx.x;
    const int b  = blockIdx.x >> 8;
    const int n0 = (blockIdx.x & 255) * 8;
    const int h  = t >> 5;
    const int d  = t & 31;

    __shared__ float red1[4][8], red2[4][8];

    const float gma = gamma[t];
    const float bta = beta[t];
    float ys[8];

#pragma unroll
    for (int r = 0; r < 8; ++r) {
        const int n = n0 + r;
        float accv = 0.f, rsum = 0.f;
#pragma unroll
        for (int spp = 0; spp < SPLIT; ++spp) {
            accv += g_part[(size_t)((spp * 2 + b) * NN + n) * 128 + t];
            rsum += g_psum[((size_t)(spp * 2 + b) * NN + n) * 4 + h];
        }
        float y = accv / rsum + g_h[(size_t)(b * NN + n) * 128 + t];
        ys[r] = y;
        float s1 = y, s2 = y * y;
#pragma unroll
        for (int off = 16; off; off >>= 1) {
            s1 += __shfl_xor_sync(0xffffffffu, s1, off);
            s2 += __shfl_xor_sync(0xffffffffu, s2, off);
        }
        if (d == 0) { red1[h][r] = s1; red2[h][r] = s2; }
    }
    __syncthreads();
#pragma unroll
    for (int r = 0; r < 8; ++r) {
        float s1 = red1[0][r] + red1[1][r] + red1[2][r] + red1[3][r];
        float s2 = red2[0][r] + red2[1][r] + red2[2][r] + red2[3][r];
        float mu  = s1 * (1.f / 128.f);
        float var = s2 * (1.f / 128.f) - mu * mu;
        float inv = rsqrtf(var + 1e-5f);
        out[(size_t)(b * NN + n0 + r) * 128 + t] = (ys[r] - mu) * inv * gma + bta;
    }
}

extern "C" void kernel_launch(void* const* d_in, const int* in_sizes, int n_in,
                              void* d_out, int out_size) {
    const float* x     = (const float*)d_in[0];
    const int*   adj   = (const int*)  d_in[1];
    const float* w     = (const float*)d_in[2];
    const float* a     = (const float*)d_in[3];
    const float* gamma = (const float*)d_in[4];
    const float* beta  = (const float*)d_in[5];

    static int smem_set = 0;
    if (!smem_set) {
        cudaFuncSetAttribute(k2_attn, cudaFuncAttributeMaxDynamicSharedMemorySize, SMEM_SZ);
        smem_set = 1;
    }

    k1_proj<<<512, 128>>>(x, w, a);
    k2_attn<<<16 * SPLIT * 2, 256, SMEM_SZ>>>(adj);
    k3_epi<<<512, 128>>>(gamma, beta, (float*)d_out);
}